// round 12
// baseline (speedup 1.0000x reference)
#include <cuda_runtime.h>
#include <cuda_bf16.h>
#include <cstdint>

#define NS 100000
#define NT 50000
#define NE 600000
#define CH 128
#define NR 7
#define NTY 4
#define KREL (NR * CH)              // 896
#define KORIG (NR * CH + NTY * CH)  // 1408
#define NITER (KORIG / 16)          // 88 groups of 16 orig-k
#define NGRPREL 56                  // relation groups

// ---------------- device scratch ----------------
__device__ float g_agg[(size_t)NT * NR * CH];   // 179.2 MB
__device__ float g_cnt[NT * NR];                // count -> 0 or 1/cnt
__device__ unsigned g_B2[128 * NITER * 16];     // [bh x16 (32B)][bl x16 (32B)] per (n, group)
__device__ int g_tycnt[NTY];
__device__ int g_tycur[NTY];
__device__ int g_perm[NT];

// ---------------- helpers ----------------
__device__ __forceinline__ uint32_t smem_u32(const void* p) {
    uint32_t a;
    asm("{ .reg .u64 t; cvta.to.shared.u64 t, %1; cvt.u32.u64 %0, t; }" : "=r"(a) : "l"(p));
    return a;
}
static __device__ __forceinline__ void split2(float a, uint16_t& h, uint16_t& l) {
    __nv_bfloat16 hb = __float2bfloat16_rn(a);
    float hf = __bfloat162float(hb);
    __nv_bfloat16 lb = __float2bfloat16_rn(a - hf);
    h = __bfloat16_as_ushort(hb);
    l = __bfloat16_as_ushort(lb);
}
__device__ __forceinline__ void ldsm4(uint32_t* r, uint32_t addr) {
    asm volatile("ldmatrix.sync.aligned.m8n8.x4.shared.b16 {%0,%1,%2,%3}, [%4];"
                 : "=r"(r[0]), "=r"(r[1]), "=r"(r[2]), "=r"(r[3]) : "r"(addr));
}
__device__ __forceinline__ void mma16816(float* d, const uint32_t* a, const uint32_t* b) {
    asm volatile("mma.sync.aligned.m16n8k16.row.col.f32.bf16.bf16.f32 "
                 "{%0,%1,%2,%3}, {%4,%5,%6,%7}, {%8,%9}, {%0,%1,%2,%3};"
                 : "+f"(d[0]), "+f"(d[1]), "+f"(d[2]), "+f"(d[3])
                 : "r"(a[0]), "r"(a[1]), "r"(a[2]), "r"(a[3]), "r"(b[0]), "r"(b[1]));
}
__device__ __forceinline__ void cpasync16(uint32_t dst, const void* src) {
    asm volatile("cp.async.cg.shared.global [%0], [%1], 16;" :: "r"(dst), "l"(src) : "memory");
}
#define CP_COMMIT() asm volatile("cp.async.commit_group;" ::: "memory")
#define CP_WAIT1()  asm volatile("cp.async.wait_group 1;" ::: "memory")

// ---------------- kernel 1: zero agg/cnt/sort-state + build split B ----------------
__global__ void k_init(const float* __restrict__ rel_w, const float* __restrict__ root_w) {
    size_t i = (size_t)blockIdx.x * blockDim.x + threadIdx.x;
    const size_t n_agg4 = ((size_t)NT * NR * CH) / 4;
    const size_t n_cnt4 = (NT * NR) / 4;
    float4 z = make_float4(0.f, 0.f, 0.f, 0.f);
    if (i < n_agg4) reinterpret_cast<float4*>(g_agg)[i] = z;
    if (i < n_cnt4) reinterpret_cast<float4*>(g_cnt)[i] = z;
    if (i < NTY) { g_tycnt[i] = 0; g_tycur[i] = 0; }
    if (i < (size_t)128 * NITER) {
        int n = (int)(i / NITER);
        int g = (int)(i % NITER);
        uint32_t bh[8], bl[8];
        #pragma unroll
        for (int jp = 0; jp < 8; jp++) {
            uint16_t h0, l0, h1, l1;
            #pragma unroll
            for (int s = 0; s < 2; s++) {
                int kg = g * 16 + jp * 2 + s;
                float w;
                if (kg < KREL) {
                    int r = kg >> 7, kk = kg & 127;
                    w = rel_w[(size_t)r * CH * CH + (size_t)n * CH + kk];
                } else {
                    int j = kg - KREL;
                    int ty = j >> 7, kk = j & 127;
                    w = root_w[(size_t)ty * CH * CH + (size_t)n * CH + kk];
                }
                if (s == 0) split2(w, h0, l0); else split2(w, h1, l1);
            }
            bh[jp] = (uint32_t)h0 | ((uint32_t)h1 << 16);
            bl[jp] = (uint32_t)l0 | ((uint32_t)l1 << 16);
        }
        uint4* d4 = reinterpret_cast<uint4*>(g_B2 + i * 16);
        d4[0] = make_uint4(bh[0], bh[1], bh[2], bh[3]);
        d4[1] = make_uint4(bh[4], bh[5], bh[6], bh[7]);
        d4[2] = make_uint4(bl[0], bl[1], bl[2], bl[3]);
        d4[3] = make_uint4(bl[4], bl[5], bl[6], bl[7]);
    }
}

// ---------------- kernel 2: edge scatter + warp-aggregated type histogram ----------------
__global__ void k_scatter(const float* __restrict__ x_src,
                          const int* __restrict__ edge_src,
                          const int* __restrict__ edge_dst,
                          const int* __restrict__ edge_type,
                          const int* __restrict__ tgt_type) {
    int gtid = blockIdx.x * blockDim.x + threadIdx.x;
    int lane = gtid & 31;
    if (gtid - lane < NT) {
        int ty = (gtid < NT) ? tgt_type[gtid] : -1;
        #pragma unroll
        for (int q = 0; q < NTY; q++) {
            unsigned b = __ballot_sync(0xffffffffu, ty == q);
            if (b && lane == (__ffs(b) - 1)) atomicAdd(&g_tycnt[q], __popc(b));
        }
    }
    int e = gtid >> 5;
    if (e >= NE) return;
    int src = edge_src[e];
    int dst = edge_dst[e];
    int r   = edge_type[e];
    float4 v = reinterpret_cast<const float4*>(x_src + (size_t)src * CH)[lane];
    float* a = g_agg + ((size_t)dst * NR + r) * CH + lane * 4;
    asm volatile("red.global.add.v4.f32 [%0], {%1, %2, %3, %4};"
                 :: "l"(a), "f"(v.x), "f"(v.y), "f"(v.z), "f"(v.w) : "memory");
    if (lane == 0) {
        float* c = &g_cnt[(size_t)dst * NR + r];
        asm volatile("red.global.add.f32 [%0], %1;" :: "l"(c), "f"(1.0f) : "memory");
    }
}

// ---------------- kernel 3: cnt -> inv (0 if empty) + warp-aggregated perm build ----------------
__global__ void k_inv(const int* __restrict__ tgt_type) {
    int i = blockIdx.x * blockDim.x + threadIdx.x;
    int lane = threadIdx.x & 31;
    if (i < NT * NR) {
        float c = g_cnt[i];
        g_cnt[i] = (c == 0.f) ? 0.f : 1.0f / c;
    }
    if (i - lane < NT) {
        int ty = (i < NT) ? tgt_type[i] : -1;
        int off = 0;
        #pragma unroll
        for (int q = 0; q < NTY; q++) {
            unsigned b = __ballot_sync(0xffffffffu, ty == q);
            if (b) {
                int leader = __ffs(b) - 1;
                int base = 0;
                if (lane == leader) base = atomicAdd(&g_tycur[q], __popc(b));
                base = __shfl_sync(0xffffffffu, base, leader);
                if (ty == q) {
                    int rank = __popc(b & ((1u << lane) - 1u));
                    g_perm[off + base + rank] = i;
                }
            }
            off += g_tycnt[q];
        }
    }
}

// ---------------- kernel 4: bf16x3 GEMM, A-ring x4 + B-ring x3, 1 sync/iter ----------------
// BM=128, BN=128, 8 warps (4m x 2n), warp tile m32n64.
#define PITCH 80
#define SM_ABUF (128 * PITCH)    // 10240
#define SM_BBUF (128 * PITCH)    // 10240
#define SM_BOFF (4 * SM_ABUF)    // 40960
#define SM_TOT  (4 * SM_ABUF + 3 * SM_BBUF)   // 71680

__global__ void __launch_bounds__(256, 2) k_gemm_mma(const float* __restrict__ x_target,
                                                     const int* __restrict__ tgt_type,
                                                     const float* __restrict__ root_b,
                                                     float* __restrict__ out) {
    extern __shared__ __align__(16) char smem[];
    const uint32_t sb = smem_u32(smem);
    const int tid = threadIdx.x;
    const int lane = tid & 31;
    const int wid = tid >> 5;
    const int wm = wid >> 1;      // 0..3
    const int wn = wid & 1;       // 0..1
    const int t0 = blockIdx.x * 128;

    // ---- fill roles: 2 threads per row, each 8 orig-k ----
    const int arow = tid >> 1;
    const int h    = tid & 1;
    const int ti = t0 + arow;
    const bool rv = (ti < NT);
    const int rA = rv ? g_perm[ti] : 0;
    const int myty = tgt_type[rA];
    const float* xrow = x_target + (size_t)rA * CH;

    // ---- tile type range + iteration schedule ----
    const int tyLo = tgt_type[g_perm[t0]];
    const int tyHi = tgt_type[g_perm[(t0 + 127 < NT) ? (t0 + 127) : (NT - 1)]];
    const int nseq = NGRPREL + 8 * (tyHi - tyLo + 1);
    const int rootBase = NGRPREL + 8 * tyLo;

    float acc[2][8][4];
    #pragma unroll
    for (int m = 0; m < 2; m++)
        #pragma unroll
        for (int n = 0; n < 8; n++)
            #pragma unroll
            for (int j = 0; j < 4; j++) acc[m][n][j] = 0.f;

    float av[2][8];   // 2-deep A register prefetch
    auto loadA = [&](float* dstv, int s) {
        const int g = (s < NGRPREL) ? s : rootBase + (s - NGRPREL);
        const int kb = (g & 7) * 16 + h * 8;
        bool doload = false;
        const float* p = nullptr;
        float scale = 1.f;
        if (g < NGRPREL) {
            const int rblk = g >> 3;
            if (rv) {
                const size_t base = (size_t)rA * NR + rblk;
                const float inv = g_cnt[base];
                if (inv != 0.f) { doload = true; p = g_agg + base * CH + kb; scale = inv; }
            }
        } else {
            const int rblk2 = (g >> 3) - NR;
            if (rv && myty == rblk2) { doload = true; p = xrow + kb; }
        }
        if (doload) {
            float4 v0 = *reinterpret_cast<const float4*>(p);
            float4 v1 = *reinterpret_cast<const float4*>(p + 4);
            dstv[0] = v0.x * scale; dstv[1] = v0.y * scale; dstv[2] = v0.z * scale; dstv[3] = v0.w * scale;
            dstv[4] = v1.x * scale; dstv[5] = v1.y * scale; dstv[6] = v1.z * scale; dstv[7] = v1.w * scale;
        } else {
            #pragma unroll
            for (int j = 0; j < 8; j++) dstv[j] = 0.f;
        }
    };

    auto storeA = [&](const float* srcv, int s) {
        uint16_t hh[8], ll[8];
        #pragma unroll
        for (int j = 0; j < 8; j++) split2(srcv[j], hh[j], ll[j]);
        uint4 hp = make_uint4((uint32_t)hh[0] | ((uint32_t)hh[1] << 16),
                              (uint32_t)hh[2] | ((uint32_t)hh[3] << 16),
                              (uint32_t)hh[4] | ((uint32_t)hh[5] << 16),
                              (uint32_t)hh[6] | ((uint32_t)hh[7] << 16));
        uint4 lp = make_uint4((uint32_t)ll[0] | ((uint32_t)ll[1] << 16),
                              (uint32_t)ll[2] | ((uint32_t)ll[3] << 16),
                              (uint32_t)ll[4] | ((uint32_t)ll[5] << 16),
                              (uint32_t)ll[6] | ((uint32_t)ll[7] << 16));
        char* rb = smem + (s & 3) * SM_ABUF + arow * PITCH + h * 16;
        *reinterpret_cast<uint4*>(rb)      = hp;
        *reinterpret_cast<uint4*>(rb + 32) = lp;
    };

    auto issueB = [&](int s) {
        const int g = (s < NGRPREL) ? s : rootBase + (s - NGRPREL);
        uint32_t dst = sb + SM_BOFF + (uint32_t)(s % 3) * SM_BBUF + arow * PITCH + h * 32;
        const char* src = reinterpret_cast<const char*>(
            g_B2 + ((size_t)arow * NITER + g) * 16 + h * 8);
        cpasync16(dst, src);
        cpasync16(dst + 16, src + 16);
    };

    // ---- prologue ----
    loadA(av[0], 0);
    loadA(av[1], 1);
    storeA(av[0], 0);
    issueB(0); CP_COMMIT();
    issueB(1); CP_COMMIT();

    // ldmatrix address components
    const int a_rb = wm * 32 + (lane & 15);
    const int a_cb = (lane >> 4) * 16;
    const int b_rb = wn * 64 + ((lane >> 4) << 3) + (lane & 7);
    const int b_cb = ((lane >> 3) & 1) * 16;

    for (int s = 0; s < nseq; s++) {
        CP_WAIT1();           // B(s) landed (newest outstanding is B(s+1))
        __syncthreads();      // A(s) + B(s) visible; orders ring reuse

        if (s + 2 < nseq) issueB(s + 2);
        CP_COMMIT();          // always commit (possibly empty) to keep group count uniform
        if (s + 1 < nseq) storeA(av[(s + 1) & 1], s + 1);
        if (s + 2 < nseq) loadA(av[s & 1], s + 2);

        // ---- compute(s): 3-term pairing with fragment reuse ----
        const uint32_t Au = sb + (uint32_t)(s & 3) * SM_ABUF;
        const uint32_t Bu = sb + SM_BOFF + (uint32_t)(s % 3) * SM_BBUF;
        uint32_t ah[2][4], al[2][4];
        #pragma unroll
        for (int mt = 0; mt < 2; mt++) {
            uint32_t aaddr = Au + (a_rb + mt * 16) * PITCH + a_cb;
            ldsm4(ah[mt], aaddr);
            ldsm4(al[mt], aaddr + 32);
        }
        #pragma unroll
        for (int nt = 0; nt < 4; nt++) {
            uint32_t bh[4], bl[4];
            uint32_t baddr = Bu + (b_rb + nt * 16) * PITCH + b_cb;
            ldsm4(bh, baddr);
            ldsm4(bl, baddr + 32);
            #pragma unroll
            for (int mt = 0; mt < 2; mt++) {
                mma16816(acc[mt][2 * nt],     ah[mt], &bh[0]);
                mma16816(acc[mt][2 * nt + 1], ah[mt], &bh[2]);
                mma16816(acc[mt][2 * nt],     al[mt], &bh[0]);
                mma16816(acc[mt][2 * nt + 1], al[mt], &bh[2]);
                mma16816(acc[mt][2 * nt],     ah[mt], &bl[0]);
                mma16816(acc[mt][2 * nt + 1], ah[mt], &bl[2]);
            }
        }
        // single barrier per iteration (ring depth covers reuse hazards)
    }

    // ---- epilogue: permuted store + per-type bias ----
    const int g  = lane >> 2;
    const int tg = lane & 3;
    #pragma unroll
    for (int mt = 0; mt < 2; mt++) {
        const int i0 = t0 + wm * 32 + mt * 16 + g;
        const int i1 = i0 + 8;
        const bool v0 = (i0 < NT), v1 = (i1 < NT);
        const int r0 = v0 ? g_perm[i0] : 0;
        const int r1 = v1 ? g_perm[i1] : 0;
        const float* rb0 = root_b + (size_t)tgt_type[r0] * CH;
        const float* rb1 = root_b + (size_t)tgt_type[r1] * CH;
        #pragma unroll
        for (int j = 0; j < 8; j++) {
            const int col = wn * 64 + j * 8 + tg * 2;
            if (v0) {
                float2 bb = *reinterpret_cast<const float2*>(rb0 + col);
                float2 w = make_float2(acc[mt][j][0] + bb.x, acc[mt][j][1] + bb.y);
                *reinterpret_cast<float2*>(out + (size_t)r0 * CH + col) = w;
            }
            if (v1) {
                float2 bb = *reinterpret_cast<const float2*>(rb1 + col);
                float2 w = make_float2(acc[mt][j][2] + bb.x, acc[mt][j][3] + bb.y);
                *reinterpret_cast<float2*>(out + (size_t)r1 * CH + col) = w;
            }
        }
    }
}

// ---------------- launch ----------------
extern "C" void kernel_launch(void* const* d_in, const int* in_sizes, int n_in,
                              void* d_out, int out_size) {
    const float* x_src     = (const float*)d_in[0];
    const float* x_target  = (const float*)d_in[1];
    const float* rel_w     = (const float*)d_in[2];
    const float* root_w    = (const float*)d_in[3];
    const float* root_b    = (const float*)d_in[4];
    const int*   edge_src  = (const int*)d_in[5];
    const int*   edge_dst  = (const int*)d_in[6];
    const int*   edge_type = (const int*)d_in[7];
    const int*   tgt_type  = (const int*)d_in[8];
    float* out = (float*)d_out;

    (void)in_sizes; (void)n_in; (void)out_size;

    cudaFuncSetAttribute(k_gemm_mma, cudaFuncAttributeMaxDynamicSharedMemorySize, SM_TOT);

    {
        size_t n4 = ((size_t)NT * NR * CH) / 4;
        int blocks = (int)((n4 + 255) / 256);
        k_init<<<blocks, 256>>>(rel_w, root_w);
    }
    k_scatter<<<(NE + 7) / 8, 256>>>(x_src, edge_src, edge_dst, edge_type, tgt_type);
    k_inv<<<(NT * NR + 255) / 256, 256>>>(tgt_type);
    k_gemm_mma<<<(NT + 127) / 128, 256, SM_TOT>>>(x_target, tgt_type, root_b, out);
}

// round 13
// speedup vs baseline: 1.2480x; 1.2480x over previous
#include <cuda_runtime.h>
#include <cuda_bf16.h>
#include <cstdint>

#define NS 100000
#define NT 50000
#define NE 600000
#define CH 128
#define NR 7
#define NTY 4
#define KREL (NR * CH)              // 896
#define KORIG (NR * CH + NTY * CH)  // 1408
#define NITER (KORIG / 16)          // 88 groups of 16 orig-k
#define NGRPREL 56                  // relation groups

// ---------------- device scratch ----------------
__device__ float g_agg[(size_t)NT * NR * CH];   // 179.2 MB
__device__ float g_cnt[NT * NR];                // count -> 0 or 1/cnt
__device__ unsigned g_B2[128 * NITER * 16];     // [bh x16 (32B)][bl x16 (32B)] per (n, group)
__device__ int g_tycnt[NTY];
__device__ int g_tycur[NTY];
__device__ int g_perm[NT];

// ---------------- helpers ----------------
__device__ __forceinline__ uint32_t smem_u32(const void* p) {
    uint32_t a;
    asm("{ .reg .u64 t; cvta.to.shared.u64 t, %1; cvt.u32.u64 %0, t; }" : "=r"(a) : "l"(p));
    return a;
}
static __device__ __forceinline__ void split2(float a, uint16_t& h, uint16_t& l) {
    __nv_bfloat16 hb = __float2bfloat16_rn(a);
    float hf = __bfloat162float(hb);
    __nv_bfloat16 lb = __float2bfloat16_rn(a - hf);
    h = __bfloat16_as_ushort(hb);
    l = __bfloat16_as_ushort(lb);
}
__device__ __forceinline__ void ldsm4(uint32_t* r, uint32_t addr) {
    asm volatile("ldmatrix.sync.aligned.m8n8.x4.shared.b16 {%0,%1,%2,%3}, [%4];"
                 : "=r"(r[0]), "=r"(r[1]), "=r"(r[2]), "=r"(r[3]) : "r"(addr));
}
__device__ __forceinline__ void mma16816(float* d, const uint32_t* a, const uint32_t* b) {
    asm volatile("mma.sync.aligned.m16n8k16.row.col.f32.bf16.bf16.f32 "
                 "{%0,%1,%2,%3}, {%4,%5,%6,%7}, {%8,%9}, {%0,%1,%2,%3};"
                 : "+f"(d[0]), "+f"(d[1]), "+f"(d[2]), "+f"(d[3])
                 : "r"(a[0]), "r"(a[1]), "r"(a[2]), "r"(a[3]), "r"(b[0]), "r"(b[1]));
}
__device__ __forceinline__ void cpasync16(uint32_t dst, const void* src) {
    asm volatile("cp.async.cg.shared.global [%0], [%1], 16;" :: "r"(dst), "l"(src) : "memory");
}
#define CP_COMMIT() asm volatile("cp.async.commit_group;" ::: "memory")
#define CP_WAIT1()  asm volatile("cp.async.wait_group 1;" ::: "memory")

// ---------------- kernel 1: zero agg/cnt/sort-state + build split B ----------------
__global__ void k_init(const float* __restrict__ rel_w, const float* __restrict__ root_w) {
    size_t i = (size_t)blockIdx.x * blockDim.x + threadIdx.x;
    const size_t n_agg4 = ((size_t)NT * NR * CH) / 4;
    const size_t n_cnt4 = (NT * NR) / 4;
    float4 z = make_float4(0.f, 0.f, 0.f, 0.f);
    if (i < n_agg4) reinterpret_cast<float4*>(g_agg)[i] = z;
    if (i < n_cnt4) reinterpret_cast<float4*>(g_cnt)[i] = z;
    if (i < NTY) { g_tycnt[i] = 0; g_tycur[i] = 0; }
    if (i < (size_t)128 * NITER) {
        int n = (int)(i / NITER);
        int g = (int)(i % NITER);
        uint32_t bh[8], bl[8];
        #pragma unroll
        for (int jp = 0; jp < 8; jp++) {
            uint16_t h0, l0, h1, l1;
            #pragma unroll
            for (int s = 0; s < 2; s++) {
                int kg = g * 16 + jp * 2 + s;
                float w;
                if (kg < KREL) {
                    int r = kg >> 7, kk = kg & 127;
                    w = rel_w[(size_t)r * CH * CH + (size_t)n * CH + kk];
                } else {
                    int j = kg - KREL;
                    int ty = j >> 7, kk = j & 127;
                    w = root_w[(size_t)ty * CH * CH + (size_t)n * CH + kk];
                }
                if (s == 0) split2(w, h0, l0); else split2(w, h1, l1);
            }
            bh[jp] = (uint32_t)h0 | ((uint32_t)h1 << 16);
            bl[jp] = (uint32_t)l0 | ((uint32_t)l1 << 16);
        }
        uint4* d4 = reinterpret_cast<uint4*>(g_B2 + i * 16);
        d4[0] = make_uint4(bh[0], bh[1], bh[2], bh[3]);
        d4[1] = make_uint4(bh[4], bh[5], bh[6], bh[7]);
        d4[2] = make_uint4(bl[0], bl[1], bl[2], bl[3]);
        d4[3] = make_uint4(bl[4], bl[5], bl[6], bl[7]);
    }
}

// ---------------- kernel 2: edge scatter + warp-aggregated type histogram ----------------
__global__ void k_scatter(const float* __restrict__ x_src,
                          const int* __restrict__ edge_src,
                          const int* __restrict__ edge_dst,
                          const int* __restrict__ edge_type,
                          const int* __restrict__ tgt_type) {
    int gtid = blockIdx.x * blockDim.x + threadIdx.x;
    int lane = gtid & 31;
    if (gtid - lane < NT) {
        int ty = (gtid < NT) ? tgt_type[gtid] : -1;
        #pragma unroll
        for (int q = 0; q < NTY; q++) {
            unsigned b = __ballot_sync(0xffffffffu, ty == q);
            if (b && lane == (__ffs(b) - 1)) atomicAdd(&g_tycnt[q], __popc(b));
        }
    }
    int e = gtid >> 5;
    if (e >= NE) return;
    int src = edge_src[e];
    int dst = edge_dst[e];
    int r   = edge_type[e];
    float4 v = reinterpret_cast<const float4*>(x_src + (size_t)src * CH)[lane];
    float* a = g_agg + ((size_t)dst * NR + r) * CH + lane * 4;
    asm volatile("red.global.add.v4.f32 [%0], {%1, %2, %3, %4};"
                 :: "l"(a), "f"(v.x), "f"(v.y), "f"(v.z), "f"(v.w) : "memory");
    if (lane == 0) {
        float* c = &g_cnt[(size_t)dst * NR + r];
        asm volatile("red.global.add.f32 [%0], %1;" :: "l"(c), "f"(1.0f) : "memory");
    }
}

// ---------------- kernel 3: cnt -> inv (0 if empty) + warp-aggregated perm build ----------------
__global__ void k_inv(const int* __restrict__ tgt_type) {
    int i = blockIdx.x * blockDim.x + threadIdx.x;
    int lane = threadIdx.x & 31;
    if (i < NT * NR) {
        float c = g_cnt[i];
        g_cnt[i] = (c == 0.f) ? 0.f : 1.0f / c;
    }
    if (i - lane < NT) {
        int ty = (i < NT) ? tgt_type[i] : -1;
        int off = 0;
        #pragma unroll
        for (int q = 0; q < NTY; q++) {
            unsigned b = __ballot_sync(0xffffffffu, ty == q);
            if (b) {
                int leader = __ffs(b) - 1;
                int base = 0;
                if (lane == leader) base = atomicAdd(&g_tycur[q], __popc(b));
                base = __shfl_sync(0xffffffffu, base, leader);
                if (ty == q) {
                    int rank = __popc(b & ((1u << lane) - 1u));
                    g_perm[off + base + rank] = i;
                }
            }
            off += g_tycnt[q];
        }
    }
}

// ---------------- kernel 4: bf16x3 GEMM, 1 sync/iter, A x2 + B x2 double buffers ----------------
// Iter s: sync; issueB(s+1)->slot (s+1)&1; wait1 (B(s) done, B(s+1) flying);
//         storeA(s+1); loadA(s+2); compute(s).
#define PITCH 80
#define SM_ABUF (128 * PITCH)    // 10240
#define SM_BBUF (128 * PITCH)    // 10240
#define SM_TOT  (2 * SM_ABUF + 2 * SM_BBUF)   // 40960

__global__ void __launch_bounds__(256, 2) k_gemm_mma(const float* __restrict__ x_target,
                                                     const int* __restrict__ tgt_type,
                                                     const float* __restrict__ root_b,
                                                     float* __restrict__ out) {
    __shared__ __align__(16) char smem[SM_TOT];
    const uint32_t sb = smem_u32(smem);
    const int tid = threadIdx.x;
    const int lane = tid & 31;
    const int wid = tid >> 5;
    const int wm = wid >> 1;      // 0..3
    const int wn = wid & 1;       // 0..1
    const int t0 = blockIdx.x * 128;

    const int arow = tid >> 1;
    const int h    = tid & 1;
    const int ti = t0 + arow;
    const bool rv = (ti < NT);
    const int rA = rv ? g_perm[ti] : 0;
    const int myty = tgt_type[rA];
    const float* xrow = x_target + (size_t)rA * CH;

    const int tyLo = tgt_type[g_perm[t0]];
    const int tyHi = tgt_type[g_perm[(t0 + 127 < NT) ? (t0 + 127) : (NT - 1)]];
    const int nseq = NGRPREL + 8 * (tyHi - tyLo + 1);
    const int rootBase = NGRPREL + 8 * tyLo;

    float acc[2][8][4];
    #pragma unroll
    for (int m = 0; m < 2; m++)
        #pragma unroll
        for (int n = 0; n < 8; n++)
            #pragma unroll
            for (int j = 0; j < 4; j++) acc[m][n][j] = 0.f;

    float av[8];
    auto loadA = [&](int s) {
        const int g = (s < NGRPREL) ? s : rootBase + (s - NGRPREL);
        const int kb = (g & 7) * 16 + h * 8;
        bool doload = false;
        const float* p = nullptr;
        float scale = 1.f;
        if (g < NGRPREL) {
            const int rblk = g >> 3;
            if (rv) {
                const size_t base = (size_t)rA * NR + rblk;
                const float inv = g_cnt[base];
                if (inv != 0.f) { doload = true; p = g_agg + base * CH + kb; scale = inv; }
            }
        } else {
            const int rblk2 = (g >> 3) - NR;
            if (rv && myty == rblk2) { doload = true; p = xrow + kb; }
        }
        if (doload) {
            float4 v0 = *reinterpret_cast<const float4*>(p);
            float4 v1 = *reinterpret_cast<const float4*>(p + 4);
            av[0] = v0.x * scale; av[1] = v0.y * scale; av[2] = v0.z * scale; av[3] = v0.w * scale;
            av[4] = v1.x * scale; av[5] = v1.y * scale; av[6] = v1.z * scale; av[7] = v1.w * scale;
        } else {
            #pragma unroll
            for (int j = 0; j < 8; j++) av[j] = 0.f;
        }
    };

    auto storeA = [&](int s) {
        uint16_t hh[8], ll[8];
        #pragma unroll
        for (int j = 0; j < 8; j++) split2(av[j], hh[j], ll[j]);
        uint4 hp = make_uint4((uint32_t)hh[0] | ((uint32_t)hh[1] << 16),
                              (uint32_t)hh[2] | ((uint32_t)hh[3] << 16),
                              (uint32_t)hh[4] | ((uint32_t)hh[5] << 16),
                              (uint32_t)hh[6] | ((uint32_t)hh[7] << 16));
        uint4 lp = make_uint4((uint32_t)ll[0] | ((uint32_t)ll[1] << 16),
                              (uint32_t)ll[2] | ((uint32_t)ll[3] << 16),
                              (uint32_t)ll[4] | ((uint32_t)ll[5] << 16),
                              (uint32_t)ll[6] | ((uint32_t)ll[7] << 16));
        char* rb = smem + (s & 1) * SM_ABUF + arow * PITCH + h * 16;
        *reinterpret_cast<uint4*>(rb)      = hp;
        *reinterpret_cast<uint4*>(rb + 32) = lp;
    };

    auto issueB = [&](int s) {
        const int g = (s < NGRPREL) ? s : rootBase + (s - NGRPREL);
        uint32_t dst = sb + 2 * SM_ABUF + (uint32_t)(s & 1) * SM_BBUF + arow * PITCH + h * 32;
        const char* src = reinterpret_cast<const char*>(
            g_B2 + ((size_t)arow * NITER + g) * 16 + h * 8);
        cpasync16(dst, src);
        cpasync16(dst + 16, src + 16);
    };

    // ---- prologue: A(0) in smem, av = A(1); B(0) committed ----
    loadA(0);
    storeA(0);
    loadA(1);
    issueB(0); CP_COMMIT();

    const int a_rb = wm * 32 + (lane & 15);
    const int a_cb = (lane >> 4) * 16;
    const int b_rb = wn * 64 + ((lane >> 4) << 3) + (lane & 7);
    const int b_cb = ((lane >> 3) & 1) * 16;

    for (int s = 0; s < nseq; s++) {
        __syncthreads();      // orders A/B slot reuse across iterations; A(s) visible

        // issue B(s+1) into slot (s+1)&1 (last read by compute(s-1), pre-barrier)
        if (s + 1 < nseq) issueB(s + 1);
        CP_COMMIT();          // uniform group count (possibly empty at tail)
        CP_WAIT1();           // <=1 group pending => B(s) landed; B(s+1) still flying

        if (s + 1 < nseq) {
            storeA(s + 1);                     // av holds A(s+1)
            if (s + 2 < nseq) loadA(s + 2);    // prefetch A(s+2) into av
        }

        const uint32_t Au = sb + (uint32_t)(s & 1) * SM_ABUF;
        const uint32_t Bu = sb + 2 * SM_ABUF + (uint32_t)(s & 1) * SM_BBUF;
        uint32_t ah[2][4], al[2][4];
        #pragma unroll
        for (int mt = 0; mt < 2; mt++) {
            uint32_t aaddr = Au + (a_rb + mt * 16) * PITCH + a_cb;
            ldsm4(ah[mt], aaddr);
            ldsm4(al[mt], aaddr + 32);
        }
        #pragma unroll
        for (int nt = 0; nt < 4; nt++) {
            uint32_t bh[4], bl[4];
            uint32_t baddr = Bu + (b_rb + nt * 16) * PITCH + b_cb;
            ldsm4(bh, baddr);
            ldsm4(bl, baddr + 32);
            #pragma unroll
            for (int mt = 0; mt < 2; mt++) {
                mma16816(acc[mt][2 * nt],     ah[mt], &bh[0]);
                mma16816(acc[mt][2 * nt + 1], ah[mt], &bh[2]);
                mma16816(acc[mt][2 * nt],     al[mt], &bh[0]);
                mma16816(acc[mt][2 * nt + 1], al[mt], &bh[2]);
                mma16816(acc[mt][2 * nt],     ah[mt], &bl[0]);
                mma16816(acc[mt][2 * nt + 1], ah[mt], &bl[2]);
            }
        }
    }

    // ---- epilogue: permuted store + per-type bias ----
    const int g  = lane >> 2;
    const int tg = lane & 3;
    #pragma unroll
    for (int mt = 0; mt < 2; mt++) {
        const int i0 = t0 + wm * 32 + mt * 16 + g;
        const int i1 = i0 + 8;
        const bool v0 = (i0 < NT), v1 = (i1 < NT);
        const int r0 = v0 ? g_perm[i0] : 0;
        const int r1 = v1 ? g_perm[i1] : 0;
        const float* rb0 = root_b + (size_t)tgt_type[r0] * CH;
        const float* rb1 = root_b + (size_t)tgt_type[r1] * CH;
        #pragma unroll
        for (int j = 0; j < 8; j++) {
            const int col = wn * 64 + j * 8 + tg * 2;
            if (v0) {
                float2 bb = *reinterpret_cast<const float2*>(rb0 + col);
                float2 w = make_float2(acc[mt][j][0] + bb.x, acc[mt][j][1] + bb.y);
                *reinterpret_cast<float2*>(out + (size_t)r0 * CH + col) = w;
            }
            if (v1) {
                float2 bb = *reinterpret_cast<const float2*>(rb1 + col);
                float2 w = make_float2(acc[mt][j][2] + bb.x, acc[mt][j][3] + bb.y);
                *reinterpret_cast<float2*>(out + (size_t)r1 * CH + col) = w;
            }
        }
    }
}

// ---------------- launch ----------------
extern "C" void kernel_launch(void* const* d_in, const int* in_sizes, int n_in,
                              void* d_out, int out_size) {
    const float* x_src     = (const float*)d_in[0];
    const float* x_target  = (const float*)d_in[1];
    const float* rel_w     = (const float*)d_in[2];
    const float* root_w    = (const float*)d_in[3];
    const float* root_b    = (const float*)d_in[4];
    const int*   edge_src  = (const int*)d_in[5];
    const int*   edge_dst  = (const int*)d_in[6];
    const int*   edge_type = (const int*)d_in[7];
    const int*   tgt_type  = (const int*)d_in[8];
    float* out = (float*)d_out;

    (void)in_sizes; (void)n_in; (void)out_size;

    {
        size_t n4 = ((size_t)NT * NR * CH) / 4;
        int blocks = (int)((n4 + 255) / 256);
        k_init<<<blocks, 256>>>(rel_w, root_w);
    }
    k_scatter<<<(NE + 7) / 8, 256>>>(x_src, edge_src, edge_dst, edge_type, tgt_type);
    k_inv<<<(NT * NR + 255) / 256, 256>>>(tgt_type);
    k_gemm_mma<<<(NT + 127) / 128, 256>>>(x_target, tgt_type, root_b, out);
}